// round 6
// baseline (speedup 1.0000x reference)
#include <cuda_runtime.h>
#include <cuda_bf16.h>
#include <cstdint>
#include <cstddef>

#define D_IN   96
#define D_OUT  256
#define MAXN   50000
#define MAXE   800000

// -------- scratch (device globals; no allocation allowed) --------
__device__ __align__(16) float g_agg[(size_t)MAXN * D_IN];    // 19.2 MB
__device__ __align__(16) float g_h[(size_t)MAXN * D_OUT];     // 51.2 MB
__device__ __align__(16) float g_w0r[D_IN * D_OUT];
__device__ __align__(16) float g_w1r[D_OUT * D_OUT];
__device__ __align__(16) float g_scale[D_OUT];
__device__ __align__(16) float g_shift[D_OUT];
__device__ int   g_cnt[MAXN];
__device__ int   g_off[MAXN + 1];
__device__ int   g_cur[MAXN];
__device__ int   g_csrc[MAXE];
__device__ float g_cval[MAXE];

// ---------------- helpers ----------------
__device__ __forceinline__ uint32_t f2tf32(float f) {
    uint32_t u;
    asm("cvt.rna.tf32.f32 %0, %1;" : "=r"(u) : "f"(f));
    return u;
}
__device__ __forceinline__ float tf32f(float f) { return __uint_as_float(f2tf32(f)); }

__device__ __forceinline__ uint32_t smem_u32(const void* p) {
    uint32_t a;
    asm("{ .reg .u64 t; cvta.to.shared.u64 t, %1; cvt.u32.u64 %0, t; }"
        : "=r"(a) : "l"(p));
    return a;
}

__device__ __forceinline__ void mma_tf32(float d[4], const uint32_t a[4],
                                         const uint32_t b[2], const float c[4]) {
    asm volatile(
        "mma.sync.aligned.m16n8k8.row.col.f32.tf32.tf32.f32 "
        "{%0,%1,%2,%3}, {%4,%5,%6,%7}, {%8,%9}, {%10,%11,%12,%13};"
        : "=f"(d[0]), "=f"(d[1]), "=f"(d[2]), "=f"(d[3])
        : "r"(a[0]), "r"(a[1]), "r"(a[2]), "r"(a[3]),
          "r"(b[0]), "r"(b[1]),
          "f"(c[0]), "f"(c[1]), "f"(c[2]), "f"(c[3]));
}

// -------- kernel P: zero counters + BN params + rounded weight copies --------
__global__ void prep_kernel(const float* __restrict__ gamma,
                            const float* __restrict__ beta,
                            const float* __restrict__ mean,
                            const float* __restrict__ var,
                            const float* __restrict__ W0,
                            const float* __restrict__ W1, int n) {
    int t = blockIdx.x * blockDim.x + threadIdx.x;
    if (t < n) g_cnt[t] = 0;
    if (t < D_OUT) {
        float s = gamma[t] * rsqrtf(var[t] + 1e-3f);
        g_scale[t] = s;
        g_shift[t] = beta[t] - mean[t] * s;
    }
    const int N0 = D_IN * D_OUT;
    if (t < N0)                      g_w0r[t] = tf32f(W0[t]);
    if (t < D_OUT * D_OUT)           g_w1r[t] = tf32f(W1[t]);
}

// -------- kernel H: histogram of dst --------
__global__ void hist_kernel(const int* __restrict__ dst, int E) {
    int e = blockIdx.x * blockDim.x + threadIdx.x;
    if (e < E) atomicAdd(&g_cnt[dst[e]], 1);
}

// -------- kernel S: single-block exclusive scan over counts --------
#define SCAN_T 1024
__global__ void scan_kernel(int n, int E) {
    __shared__ int part[SCAN_T];
    int t = threadIdx.x;
    int per = (n + SCAN_T - 1) / SCAN_T;
    int base = t * per;
    int s = 0;
    for (int i = 0; i < per; i++) {
        int j = base + i;
        if (j < n) s += g_cnt[j];
    }
    part[t] = s;
    __syncthreads();
    // Hillis-Steele inclusive scan
    for (int d = 1; d < SCAN_T; d <<= 1) {
        int v = (t >= d) ? part[t - d] : 0;
        __syncthreads();
        part[t] += v;
        __syncthreads();
    }
    int run = (t == 0) ? 0 : part[t - 1];
    for (int i = 0; i < per; i++) {
        int j = base + i;
        if (j < n) {
            g_off[j] = run;
            g_cur[j] = run;
            run += g_cnt[j];
        }
    }
    if (t == SCAN_T - 1) g_off[n] = E;
}

// -------- kernel F: fill CSR --------
__global__ void fill_kernel(const int* __restrict__ src,
                            const int* __restrict__ dst,
                            const float* __restrict__ vals, int E) {
    int e = blockIdx.x * blockDim.x + threadIdx.x;
    if (e >= E) return;
    int p = atomicAdd(&g_cur[dst[e]], 1);
    g_csrc[p] = src[e];
    g_cval[p] = vals[e];
}

// -------- kernel G: gather-SpMM + eps residual + tf32 round --------
// one warp per dst row; lane covers cols {lane, lane+32, lane+64}
__global__ __launch_bounds__(256) void spmm_kernel(const float* __restrict__ x,
                                                   const float* __restrict__ eps,
                                                   int n) {
    int w = (blockIdx.x * blockDim.x + threadIdx.x) >> 5;
    if (w >= n) return;
    int lane = threadIdx.x & 31;
    float e = __ldg(eps);
    const float* xr = x + (size_t)w * D_IN;
    float a0 = e * __ldg(xr + lane);
    float a1 = e * __ldg(xr + lane + 32);
    float a2 = e * __ldg(xr + lane + 64);
    int beg = g_off[w], end = g_off[w + 1];
    int j = beg;
    for (; j + 1 < end; j += 2) {
        int   s0 = g_csrc[j];     float v0 = g_cval[j];
        int   s1 = g_csrc[j + 1]; float v1 = g_cval[j + 1];
        const float* x0 = x + (size_t)s0 * D_IN;
        const float* x1 = x + (size_t)s1 * D_IN;
        float b0 = __ldg(x0 + lane), b1 = __ldg(x0 + lane + 32), b2 = __ldg(x0 + lane + 64);
        float c0 = __ldg(x1 + lane), c1 = __ldg(x1 + lane + 32), c2 = __ldg(x1 + lane + 64);
        a0 = fmaf(v0, b0, a0); a1 = fmaf(v0, b1, a1); a2 = fmaf(v0, b2, a2);
        a0 = fmaf(v1, c0, a0); a1 = fmaf(v1, c1, a1); a2 = fmaf(v1, c2, a2);
    }
    if (j < end) {
        int s0 = g_csrc[j]; float v0 = g_cval[j];
        const float* x0 = x + (size_t)s0 * D_IN;
        a0 = fmaf(v0, __ldg(x0 + lane),      a0);
        a1 = fmaf(v0, __ldg(x0 + lane + 32), a1);
        a2 = fmaf(v0, __ldg(x0 + lane + 64), a2);
    }
    float* ar = g_agg + (size_t)w * D_IN;
    ar[lane]      = tf32f(a0);
    ar[lane + 32] = tf32f(a1);
    ar[lane + 64] = tf32f(a2);
}

// ============== cp.async 3-stage pipelined TF32 mma.sync GEMM ==============
#define STAGES 3
#define SA 36
#define SB 136
#define A_BYTES (128 * SA * 4)
#define B_BYTES (32 * SB * 4)
#define STAGE_BYTES (A_BYTES + B_BYTES)
#define GEMM_SMEM (STAGES * STAGE_BYTES)

__device__ __forceinline__ void cp_async16(uint32_t dst, const void* src, uint32_t sz) {
    asm volatile("cp.async.cg.shared.global [%0], [%1], 16, %2;"
                 :: "r"(dst), "l"(src), "r"(sz) : "memory");
}
__device__ __forceinline__ void cp_commit() {
    asm volatile("cp.async.commit_group;" ::: "memory");
}

__global__ __launch_bounds__(128, 2) void pipe_gemm_kernel(
    const float* __restrict__ A, const float* __restrict__ B,
    float* __restrict__ C, int M, int Nn, int K,
    const float* __restrict__ scale, const float* __restrict__ shift,
    int relu, int round_out)
{
    extern __shared__ char smem[];
    const uint32_t sb = smem_u32(smem);

    const int tid  = threadIdx.x;
    const int lane = tid & 31;
    const int warp = tid >> 5;
    const int warpM = warp & 1;
    const int warpN = warp >> 1;
    const int gid  = lane >> 2;
    const int ctig = lane & 3;
    const int crow0 = blockIdx.y * 128;
    const int ccol0 = blockIdx.x * 128;

    float acc[4][8][4];
    #pragma unroll
    for (int mt = 0; mt < 4; mt++)
        #pragma unroll
        for (int nt = 0; nt < 8; nt++)
            #pragma unroll
            for (int i = 0; i < 4; i++) acc[mt][nt][i] = 0.f;

    auto copy_stage = [&](int s) {
        const int buf = s % STAGES;
        const uint32_t abase = sb + buf * STAGE_BYTES;
        const uint32_t bbase = abase + A_BYTES;
        const int k0 = s << 5;
        #pragma unroll
        for (int j = 0; j < 8; j++) {
            int id = tid + j * 128;
            int row = id >> 3, ch = id & 7;
            int gr = crow0 + row;
            int grc = gr < M ? gr : (M - 1);
            cp_async16(abase + (uint32_t)(row * SA + ch * 4) * 4,
                       A + (size_t)grc * K + k0 + ch * 4,
                       gr < M ? 16u : 0u);
        }
        #pragma unroll
        for (int j = 0; j < 8; j++) {
            int id = tid + j * 128;
            int row = id >> 5, ch = id & 31;
            cp_async16(bbase + (uint32_t)(row * SB + ch * 4) * 4,
                       B + (size_t)(k0 + row) * Nn + ccol0 + ch * 4, 16u);
        }
    };

    const int nst = K >> 5;
    copy_stage(0); cp_commit();
    copy_stage(1); cp_commit();

    for (int s = 0; s < nst; s++) {
        asm volatile("cp.async.wait_group 1;" ::: "memory");
        __syncthreads();
        if (s + 2 < nst) copy_stage(s + 2);
        cp_commit();

        const int buf = s % STAGES;
        const float* as = reinterpret_cast<const float*>(smem + buf * STAGE_BYTES);
        const float* bs = reinterpret_cast<const float*>(smem + buf * STAGE_BYTES + A_BYTES);

        #pragma unroll
        for (int ks = 0; ks < 4; ks++) {
            const int kk = ks * 8 + ctig;
            uint32_t af[4][4];
            #pragma unroll
            for (int mt = 0; mt < 4; mt++) {
                int m0 = warpM * 64 + mt * 16 + gid;
                af[mt][0] = __float_as_uint(as[m0 * SA + kk]);
                af[mt][1] = __float_as_uint(as[(m0 + 8) * SA + kk]);
                af[mt][2] = __float_as_uint(as[m0 * SA + kk + 4]);
                af[mt][3] = __float_as_uint(as[(m0 + 8) * SA + kk + 4]);
            }
            uint32_t bf[8][2];
            #pragma unroll
            for (int nt = 0; nt < 8; nt++) {
                int n0 = warpN * 64 + nt * 8 + gid;
                bf[nt][0] = __float_as_uint(bs[kk * SB + n0]);
                bf[nt][1] = __float_as_uint(bs[(kk + 4) * SB + n0]);
            }
            #pragma unroll
            for (int mt = 0; mt < 4; mt++)
                #pragma unroll
                for (int nt = 0; nt < 8; nt++)
                    mma_tf32(acc[mt][nt], af[mt], bf[nt], acc[mt][nt]);
        }
    }

    #pragma unroll
    for (int nt = 0; nt < 8; nt++) {
        int col = ccol0 + warpN * 64 + nt * 8 + 2 * ctig;
        float sc0 = 1.f, sc1 = 1.f, sh0 = 0.f, sh1 = 0.f;
        if (scale) {
            sc0 = __ldg(scale + col);     sc1 = __ldg(scale + col + 1);
            sh0 = __ldg(shift + col);     sh1 = __ldg(shift + col + 1);
        }
        #pragma unroll
        for (int mt = 0; mt < 4; mt++) {
            int row = crow0 + warpM * 64 + mt * 16 + gid;
            float v0 = acc[mt][nt][0], v1 = acc[mt][nt][1];
            float v2 = acc[mt][nt][2], v3 = acc[mt][nt][3];
            if (scale) {
                v0 = fmaf(v0, sc0, sh0); v1 = fmaf(v1, sc1, sh1);
                v2 = fmaf(v2, sc0, sh0); v3 = fmaf(v3, sc1, sh1);
            }
            if (relu) {
                v0 = fmaxf(v0, 0.f); v1 = fmaxf(v1, 0.f);
                v2 = fmaxf(v2, 0.f); v3 = fmaxf(v3, 0.f);
            }
            if (round_out) {
                v0 = tf32f(v0); v1 = tf32f(v1); v2 = tf32f(v2); v3 = tf32f(v3);
            }
            if (row < M)
                *reinterpret_cast<float2*>(C + (size_t)row * Nn + col) =
                    make_float2(v0, v1);
            if (row + 8 < M)
                *reinterpret_cast<float2*>(C + (size_t)(row + 8) * Nn + col) =
                    make_float2(v2, v3);
        }
    }
}

extern "C" void kernel_launch(void* const* d_in, const int* in_sizes, int n_in,
                              void* d_out, int out_size) {
    const float* x        = (const float*)d_in[0];
    const int*   adj_src  = (const int*)  d_in[1];
    const int*   adj_dst  = (const int*)  d_in[2];
    const float* adj_vals = (const float*)d_in[3];
    const float* eps      = (const float*)d_in[4];
    const float* W0       = (const float*)d_in[5];
    const float* W1       = (const float*)d_in[6];
    const float* gamma    = (const float*)d_in[7];
    const float* beta     = (const float*)d_in[8];
    const float* bn_mean  = (const float*)d_in[9];
    const float* bn_var   = (const float*)d_in[10];
    float* out = (float*)d_out;

    int N = in_sizes[0] / D_IN;
    int E = in_sizes[1];

    void* p;
    cudaGetSymbolAddress(&p, g_agg);   float* agg   = (float*)p;
    cudaGetSymbolAddress(&p, g_h);     float* h     = (float*)p;
    cudaGetSymbolAddress(&p, g_w0r);   float* w0r   = (float*)p;
    cudaGetSymbolAddress(&p, g_w1r);   float* w1r   = (float*)p;
    cudaGetSymbolAddress(&p, g_scale); float* scale = (float*)p;
    cudaGetSymbolAddress(&p, g_shift); float* shift = (float*)p;

    cudaFuncSetAttribute(pipe_gemm_kernel,
                         cudaFuncAttributeMaxDynamicSharedMemorySize, GEMM_SMEM);

    // 1) prep: zero counters, BN params, rounded weights
    int ptot = (N > D_OUT * D_OUT) ? N : D_OUT * D_OUT;
    prep_kernel<<<(ptot + 255) / 256, 256>>>(gamma, beta, bn_mean, bn_var, W0, W1, N);

    // 2) CSR build
    hist_kernel<<<(E + 255) / 256, 256>>>(adj_dst, E);
    scan_kernel<<<1, SCAN_T>>>(N, E);
    fill_kernel<<<(E + 255) / 256, 256>>>(adj_src, adj_dst, adj_vals, E);

    // 3) gather-SpMM (+ eps residual + tf32 round)
    spmm_kernel<<<(N * 32 + 255) / 256, 256>>>(x, eps, N);

    dim3 grid(D_OUT / 128, (N + 127) / 128);
    // 4) h = round_tf32(relu(BN(agg @ W0)))
    pipe_gemm_kernel<<<grid, 128, GEMM_SMEM>>>(agg, w0r, h, N, D_OUT, D_IN,
                                               scale, shift, 1, 1);
    // 5) out = h @ W1
    pipe_gemm_kernel<<<grid, 128, GEMM_SMEM>>>(h, w1r, out, N, D_OUT, D_OUT,
                                               nullptr, nullptr, 0, 0);
}

// round 7
// speedup vs baseline: 1.3128x; 1.3128x over previous
#include <cuda_runtime.h>
#include <cuda_bf16.h>
#include <cstdint>
#include <cstddef>

#define D_IN   96
#define D_OUT  256
#define MAXN   50000

// -------- scratch (device globals; no allocation allowed) --------
__device__ __align__(16) float g_agg[(size_t)MAXN * D_IN];    // 19.2 MB
__device__ __align__(16) float g_h[(size_t)MAXN * D_OUT];     // 51.2 MB
__device__ __align__(16) float g_w0r[D_IN * D_OUT];
__device__ __align__(16) float g_w1r[D_OUT * D_OUT];
__device__ __align__(16) float g_scale[D_OUT];
__device__ __align__(16) float g_shift[D_OUT];

// ---------------- helpers ----------------
__device__ __forceinline__ uint32_t f2tf32(float f) {
    uint32_t u;
    asm("cvt.rna.tf32.f32 %0, %1;" : "=r"(u) : "f"(f));
    return u;
}
__device__ __forceinline__ float tf32f(float f) { return __uint_as_float(f2tf32(f)); }

__device__ __forceinline__ uint32_t smem_u32(const void* p) {
    uint32_t a;
    asm("{ .reg .u64 t; cvta.to.shared.u64 t, %1; cvt.u32.u64 %0, t; }"
        : "=r"(a) : "l"(p));
    return a;
}

__device__ __forceinline__ void mma_tf32(float d[4], const uint32_t a[4],
                                         const uint32_t b[2], const float c[4]) {
    asm volatile(
        "mma.sync.aligned.m16n8k8.row.col.f32.tf32.tf32.f32 "
        "{%0,%1,%2,%3}, {%4,%5,%6,%7}, {%8,%9}, {%10,%11,%12,%13};"
        : "=f"(d[0]), "=f"(d[1]), "=f"(d[2]), "=f"(d[3])
        : "r"(a[0]), "r"(a[1]), "r"(a[2]), "r"(a[3]),
          "r"(b[0]), "r"(b[1]),
          "f"(c[0]), "f"(c[1]), "f"(c[2]), "f"(c[3]));
}

// -------- kernel 0: agg = eps * x --------
__global__ void init_agg_kernel(const float* __restrict__ x,
                                const float* __restrict__ eps, int n4) {
    int i = blockIdx.x * blockDim.x + threadIdx.x;
    if (i >= n4) return;
    float e = eps[0];
    float4 xv = reinterpret_cast<const float4*>(x)[i];
    reinterpret_cast<float4*>(g_agg)[i] =
        make_float4(e * xv.x, e * xv.y, e * xv.z, e * xv.w);
}

// -------- vectorized global reduction (sm_90+) --------
__device__ __forceinline__ void red_add_v4(float* addr, float4 v) {
    asm volatile("red.global.add.v4.f32 [%0], {%1, %2, %3, %4};"
                 :: "l"(addr), "f"(v.x), "f"(v.y), "f"(v.z), "f"(v.w)
                 : "memory");
}

// -------- kernel 1: edge scatter  agg[dst] += vals * x[src] --------
__global__ void edge_scatter_kernel(const float* __restrict__ x,
                                    const int* __restrict__ src,
                                    const int* __restrict__ dst,
                                    const float* __restrict__ vals, int E) {
    int idx = blockIdx.x * blockDim.x + threadIdx.x;
    int e = idx / 24;
    if (e >= E) return;
    int c = idx - e * 24;
    int s = __ldg(src + e);
    int d = __ldg(dst + e);
    float v = __ldg(vals + e);
    float4 xv = __ldg(reinterpret_cast<const float4*>(x + (size_t)s * D_IN) + c);
    red_add_v4(g_agg + (size_t)d * D_IN + c * 4,
               make_float4(v * xv.x, v * xv.y, v * xv.z, v * xv.w));
}

// -------- kernel 1b: round agg to tf32 (rna) in place --------
__global__ void round_agg_kernel(int n4) {
    int i = blockIdx.x * blockDim.x + threadIdx.x;
    if (i >= n4) return;
    float4 v = reinterpret_cast<float4*>(g_agg)[i];
    reinterpret_cast<float4*>(g_agg)[i] =
        make_float4(tf32f(v.x), tf32f(v.y), tf32f(v.z), tf32f(v.w));
}

// -------- kernel 2: BN params + rounded weight copies --------
__global__ void prep_kernel(const float* __restrict__ gamma,
                            const float* __restrict__ beta,
                            const float* __restrict__ mean,
                            const float* __restrict__ var,
                            const float* __restrict__ W0,
                            const float* __restrict__ W1) {
    int t = blockIdx.x * blockDim.x + threadIdx.x;
    if (t < D_OUT) {
        float s = gamma[t] * rsqrtf(var[t] + 1e-3f);
        g_scale[t] = s;
        g_shift[t] = beta[t] - mean[t] * s;
    }
    const int N0 = D_IN * D_OUT;
    if (t < N0)            g_w0r[t] = tf32f(W0[t]);
    if (t < D_OUT * D_OUT) g_w1r[t] = tf32f(W1[t]);
}

// ============== cp.async 3-stage pipelined TF32 mma.sync GEMM ==============
// Block 128x128, BK=32, 256 threads = 8 warps (2M x 4N), warp tile 64x32.
// A smem [m][k] stride 36 (bank = 4*gid + ctig, conflict-free);
// B smem [k][n] stride 136 (bank = 8*ctig + gid, conflict-free).
// 2 CTAs/SM -> 16 warps/SM for latency hiding.
#define STAGES 3
#define SA 36
#define SB 136
#define A_BYTES (128 * SA * 4)
#define B_BYTES (32 * SB * 4)
#define STAGE_BYTES (A_BYTES + B_BYTES)
#define GEMM_SMEM (STAGES * STAGE_BYTES)

__device__ __forceinline__ void cp_async16(uint32_t dst, const void* src, uint32_t sz) {
    asm volatile("cp.async.cg.shared.global [%0], [%1], 16, %2;"
                 :: "r"(dst), "l"(src), "r"(sz) : "memory");
}
__device__ __forceinline__ void cp_commit() {
    asm volatile("cp.async.commit_group;" ::: "memory");
}

__global__ __launch_bounds__(256, 2) void pipe_gemm_kernel(
    const float* __restrict__ A, const float* __restrict__ B,
    float* __restrict__ C, int M, int Nn, int K,
    const float* __restrict__ scale, const float* __restrict__ shift,
    int relu, int round_out)
{
    extern __shared__ char smem[];
    const uint32_t sb = smem_u32(smem);

    const int tid  = threadIdx.x;
    const int lane = tid & 31;
    const int warp = tid >> 5;
    const int warpM = warp & 1;        // 2 x 64 rows
    const int warpN = warp >> 1;       // 4 x 32 cols
    const int gid  = lane >> 2;
    const int ctig = lane & 3;
    const int crow0 = blockIdx.y * 128;
    const int ccol0 = blockIdx.x * 128;

    float acc[4][4][4];
    #pragma unroll
    for (int mt = 0; mt < 4; mt++)
        #pragma unroll
        for (int nt = 0; nt < 4; nt++)
            #pragma unroll
            for (int i = 0; i < 4; i++) acc[mt][nt][i] = 0.f;

    auto copy_stage = [&](int s) {
        const int buf = s % STAGES;
        const uint32_t abase = sb + buf * STAGE_BYTES;
        const uint32_t bbase = abase + A_BYTES;
        const int k0 = s << 5;
        #pragma unroll
        for (int j = 0; j < 4; j++) {
            int id = tid + j * 256;
            int row = id >> 3, ch = id & 7;
            int gr = crow0 + row;
            int grc = gr < M ? gr : (M - 1);
            cp_async16(abase + (uint32_t)(row * SA + ch * 4) * 4,
                       A + (size_t)grc * K + k0 + ch * 4,
                       gr < M ? 16u : 0u);
        }
        #pragma unroll
        for (int j = 0; j < 4; j++) {
            int id = tid + j * 256;
            int row = id >> 5, ch = id & 31;
            cp_async16(bbase + (uint32_t)(row * SB + ch * 4) * 4,
                       B + (size_t)(k0 + row) * Nn + ccol0 + ch * 4, 16u);
        }
    };

    const int nst = K >> 5;
    copy_stage(0); cp_commit();
    copy_stage(1); cp_commit();

    for (int s = 0; s < nst; s++) {
        asm volatile("cp.async.wait_group 1;" ::: "memory");
        __syncthreads();
        if (s + 2 < nst) copy_stage(s + 2);
        cp_commit();

        const int buf = s % STAGES;
        const float* as = reinterpret_cast<const float*>(smem + buf * STAGE_BYTES);
        const float* bs = reinterpret_cast<const float*>(smem + buf * STAGE_BYTES + A_BYTES);

        #pragma unroll
        for (int ks = 0; ks < 4; ks++) {
            const int kk = ks * 8 + ctig;
            uint32_t af[4][4];
            #pragma unroll
            for (int mt = 0; mt < 4; mt++) {
                int m0 = warpM * 64 + mt * 16 + gid;
                af[mt][0] = __float_as_uint(as[m0 * SA + kk]);
                af[mt][1] = __float_as_uint(as[(m0 + 8) * SA + kk]);
                af[mt][2] = __float_as_uint(as[m0 * SA + kk + 4]);
                af[mt][3] = __float_as_uint(as[(m0 + 8) * SA + kk + 4]);
            }
            uint32_t bf[4][2];
            #pragma unroll
            for (int nt = 0; nt < 4; nt++) {
                int n0 = warpN * 32 + nt * 8 + gid;
                bf[nt][0] = __float_as_uint(bs[kk * SB + n0]);
                bf[nt][1] = __float_as_uint(bs[(kk + 4) * SB + n0]);
            }
            #pragma unroll
            for (int mt = 0; mt < 4; mt++)
                #pragma unroll
                for (int nt = 0; nt < 4; nt++)
                    mma_tf32(acc[mt][nt], af[mt], bf[nt], acc[mt][nt]);
        }
    }

    // -------- epilogue: optional BN + ReLU (+ tf32 rounding), store --------
    #pragma unroll
    for (int nt = 0; nt < 4; nt++) {
        int col = ccol0 + warpN * 32 + nt * 8 + 2 * ctig;
        float sc0 = 1.f, sc1 = 1.f, sh0 = 0.f, sh1 = 0.f;
        if (scale) {
            sc0 = __ldg(scale + col);     sc1 = __ldg(scale + col + 1);
            sh0 = __ldg(shift + col);     sh1 = __ldg(shift + col + 1);
        }
        #pragma unroll
        for (int mt = 0; mt < 4; mt++) {
            int row = crow0 + warpM * 64 + mt * 16 + gid;
            float v0 = acc[mt][nt][0], v1 = acc[mt][nt][1];
            float v2 = acc[mt][nt][2], v3 = acc[mt][nt][3];
            if (scale) {
                v0 = fmaf(v0, sc0, sh0); v1 = fmaf(v1, sc1, sh1);
                v2 = fmaf(v2, sc0, sh0); v3 = fmaf(v3, sc1, sh1);
            }
            if (relu) {
                v0 = fmaxf(v0, 0.f); v1 = fmaxf(v1, 0.f);
                v2 = fmaxf(v2, 0.f); v3 = fmaxf(v3, 0.f);
            }
            if (round_out) {
                v0 = tf32f(v0); v1 = tf32f(v1); v2 = tf32f(v2); v3 = tf32f(v3);
            }
            if (row < M)
                *reinterpret_cast<float2*>(C + (size_t)row * Nn + col) =
                    make_float2(v0, v1);
            if (row + 8 < M)
                *reinterpret_cast<float2*>(C + (size_t)(row + 8) * Nn + col) =
                    make_float2(v2, v3);
        }
    }
}

extern "C" void kernel_launch(void* const* d_in, const int* in_sizes, int n_in,
                              void* d_out, int out_size) {
    const float* x        = (const float*)d_in[0];
    const int*   adj_src  = (const int*)  d_in[1];
    const int*   adj_dst  = (const int*)  d_in[2];
    const float* adj_vals = (const float*)d_in[3];
    const float* eps      = (const float*)d_in[4];
    const float* W0       = (const float*)d_in[5];
    const float* W1       = (const float*)d_in[6];
    const float* gamma    = (const float*)d_in[7];
    const float* beta     = (const float*)d_in[8];
    const float* bn_mean  = (const float*)d_in[9];
    const float* bn_var   = (const float*)d_in[10];
    float* out = (float*)d_out;

    int N = in_sizes[0] / D_IN;
    int E = in_sizes[1];

    void* p;
    cudaGetSymbolAddress(&p, g_agg);   float* agg   = (float*)p;
    cudaGetSymbolAddress(&p, g_h);     float* h     = (float*)p;
    cudaGetSymbolAddress(&p, g_w0r);   float* w0r   = (float*)p;
    cudaGetSymbolAddress(&p, g_w1r);   float* w1r   = (float*)p;
    cudaGetSymbolAddress(&p, g_scale); float* scale = (float*)p;
    cudaGetSymbolAddress(&p, g_shift); float* shift = (float*)p;

    cudaFuncSetAttribute(pipe_gemm_kernel,
                         cudaFuncAttributeMaxDynamicSharedMemorySize, GEMM_SMEM);

    // 0) agg = eps * x
    int n4 = N * (D_IN / 4);
    init_agg_kernel<<<(n4 + 255) / 256, 256>>>(x, eps, n4);

    // 1) scatter edges into agg (vectorized L2 reductions)
    int work = E * (D_IN / 4);
    edge_scatter_kernel<<<(work + 255) / 256, 256>>>(x, adj_src, adj_dst, adj_vals, E);

    // 2) round agg to tf32
    round_agg_kernel<<<(n4 + 255) / 256, 256>>>(n4);

    // 3) BN params + rounded weights
    prep_kernel<<<(D_OUT * D_OUT + 255) / 256, 256>>>(gamma, beta, bn_mean, bn_var, W0, W1);

    dim3 grid(D_OUT / 128, (N + 127) / 128);
    // 4) h = round_tf32(relu(BN(agg @ W0)))
    pipe_gemm_kernel<<<grid, 256, GEMM_SMEM>>>(agg, w0r, h, N, D_OUT, D_IN,
                                               scale, shift, 1, 1);
    // 5) out = h @ W1
    pipe_gemm_kernel<<<grid, 256, GEMM_SMEM>>>(h, w1r, out, N, D_OUT, D_OUT,
                                               nullptr, nullptr, 0, 0);
}

// round 8
// speedup vs baseline: 1.3403x; 1.0209x over previous
#include <cuda_runtime.h>
#include <cuda_bf16.h>
#include <cstdint>
#include <cstddef>

#define D_IN   96
#define D_OUT  256
#define MAXN   50000

// -------- scratch (device globals; no allocation allowed) --------
__device__ __align__(16) float g_agg[(size_t)MAXN * D_IN];    // 19.2 MB
__device__ __align__(16) float g_h[(size_t)MAXN * D_OUT];     // 51.2 MB
__device__ __align__(16) float g_w0r[D_IN * D_OUT];
__device__ __align__(16) float g_w1r[D_OUT * D_OUT];
__device__ __align__(16) float g_scale[D_OUT];
__device__ __align__(16) float g_shift[D_OUT];

// ---------------- helpers ----------------
__device__ __forceinline__ uint32_t f2tf32(float f) {
    uint32_t u;
    asm("cvt.rna.tf32.f32 %0, %1;" : "=r"(u) : "f"(f));
    return u;
}
__device__ __forceinline__ float tf32f(float f) { return __uint_as_float(f2tf32(f)); }

__device__ __forceinline__ uint32_t smem_u32(const void* p) {
    uint32_t a;
    asm("{ .reg .u64 t; cvta.to.shared.u64 t, %1; cvt.u32.u64 %0, t; }"
        : "=r"(a) : "l"(p));
    return a;
}

__device__ __forceinline__ void mma_tf32(float d[4], const uint32_t a[4],
                                         const uint32_t b[2], const float c[4]) {
    asm volatile(
        "mma.sync.aligned.m16n8k8.row.col.f32.tf32.tf32.f32 "
        "{%0,%1,%2,%3}, {%4,%5,%6,%7}, {%8,%9}, {%10,%11,%12,%13};"
        : "=f"(d[0]), "=f"(d[1]), "=f"(d[2]), "=f"(d[3])
        : "r"(a[0]), "r"(a[1]), "r"(a[2]), "r"(a[3]),
          "r"(b[0]), "r"(b[1]),
          "f"(c[0]), "f"(c[1]), "f"(c[2]), "f"(c[3]));
}

// -------- kernel 0: agg = eps*x  +  BN params  +  rounded weight copies --------
__global__ void init_prep_kernel(const float* __restrict__ x,
                                 const float* __restrict__ eps,
                                 const float* __restrict__ gamma,
                                 const float* __restrict__ beta,
                                 const float* __restrict__ mean,
                                 const float* __restrict__ var,
                                 const float* __restrict__ W0,
                                 const float* __restrict__ W1, int n4) {
    int t = blockIdx.x * blockDim.x + threadIdx.x;
    if (t < n4) {
        float e = eps[0];
        float4 xv = reinterpret_cast<const float4*>(x)[t];
        reinterpret_cast<float4*>(g_agg)[t] =
            make_float4(e * xv.x, e * xv.y, e * xv.z, e * xv.w);
    }
    if (t < D_OUT) {
        float s = gamma[t] * rsqrtf(var[t] + 1e-3f);
        g_scale[t] = s;
        g_shift[t] = beta[t] - mean[t] * s;
    }
    const int N0 = D_IN * D_OUT;
    if (t < N0)            g_w0r[t] = tf32f(W0[t]);
    if (t < D_OUT * D_OUT) g_w1r[t] = tf32f(W1[t]);
}

// -------- vectorized global reduction (sm_90+) --------
__device__ __forceinline__ void red_add_v4(float* addr, float4 v) {
    asm volatile("red.global.add.v4.f32 [%0], {%1, %2, %3, %4};"
                 :: "l"(addr), "f"(v.x), "f"(v.y), "f"(v.z), "f"(v.w)
                 : "memory");
}

// -------- kernel 1: edge scatter  agg[dst] += vals * x[src] --------
__global__ void edge_scatter_kernel(const float* __restrict__ x,
                                    const int* __restrict__ src,
                                    const int* __restrict__ dst,
                                    const float* __restrict__ vals, int E) {
    int idx = blockIdx.x * blockDim.x + threadIdx.x;
    int e = idx / 24;
    if (e >= E) return;
    int c = idx - e * 24;
    int s = __ldg(src + e);
    int d = __ldg(dst + e);
    float v = __ldg(vals + e);
    float4 xv = __ldg(reinterpret_cast<const float4*>(x + (size_t)s * D_IN) + c);
    red_add_v4(g_agg + (size_t)d * D_IN + c * 4,
               make_float4(v * xv.x, v * xv.y, v * xv.z, v * xv.w));
}

// ============== cp.async 3-stage pipelined TF32 mma.sync GEMM ==============
// Block 128x128, BK=32, 256 threads = 8 warps (2M x 4N), warp tile 64x32.
// A smem [m][k] stride 36 (bank = 4*gid + ctig, conflict-free);
// B smem [k][n] stride 136 (bank = 8*ctig + gid, conflict-free).
// round_a: cvt A fragments to tf32-rna in-kernel (A raw fp32 in gmem).
#define STAGES 3
#define SA 36
#define SB 136
#define A_BYTES (128 * SA * 4)
#define B_BYTES (32 * SB * 4)
#define STAGE_BYTES (A_BYTES + B_BYTES)
#define GEMM_SMEM (STAGES * STAGE_BYTES)

__device__ __forceinline__ void cp_async16(uint32_t dst, const void* src, uint32_t sz) {
    asm volatile("cp.async.cg.shared.global [%0], [%1], 16, %2;"
                 :: "r"(dst), "l"(src), "r"(sz) : "memory");
}
__device__ __forceinline__ void cp_commit() {
    asm volatile("cp.async.commit_group;" ::: "memory");
}

__global__ __launch_bounds__(256, 2) void pipe_gemm_kernel(
    const float* __restrict__ A, const float* __restrict__ B,
    float* __restrict__ C, int M, int Nn, int K,
    const float* __restrict__ scale, const float* __restrict__ shift,
    int relu, int round_out, int round_a)
{
    extern __shared__ char smem[];
    const uint32_t sb = smem_u32(smem);

    const int tid  = threadIdx.x;
    const int lane = tid & 31;
    const int warp = tid >> 5;
    const int warpM = warp & 1;        // 2 x 64 rows
    const int warpN = warp >> 1;       // 4 x 32 cols
    const int gid  = lane >> 2;
    const int ctig = lane & 3;
    const int crow0 = blockIdx.y * 128;
    const int ccol0 = blockIdx.x * 128;

    float acc[4][4][4];
    #pragma unroll
    for (int mt = 0; mt < 4; mt++)
        #pragma unroll
        for (int nt = 0; nt < 4; nt++)
            #pragma unroll
            for (int i = 0; i < 4; i++) acc[mt][nt][i] = 0.f;

    auto copy_stage = [&](int s) {
        const int buf = s % STAGES;
        const uint32_t abase = sb + buf * STAGE_BYTES;
        const uint32_t bbase = abase + A_BYTES;
        const int k0 = s << 5;
        #pragma unroll
        for (int j = 0; j < 4; j++) {
            int id = tid + j * 256;
            int row = id >> 3, ch = id & 7;
            int gr = crow0 + row;
            int grc = gr < M ? gr : (M - 1);
            cp_async16(abase + (uint32_t)(row * SA + ch * 4) * 4,
                       A + (size_t)grc * K + k0 + ch * 4,
                       gr < M ? 16u : 0u);
        }
        #pragma unroll
        for (int j = 0; j < 4; j++) {
            int id = tid + j * 256;
            int row = id >> 5, ch = id & 31;
            cp_async16(bbase + (uint32_t)(row * SB + ch * 4) * 4,
                       B + (size_t)(k0 + row) * Nn + ccol0 + ch * 4, 16u);
        }
    };

    const int nst = K >> 5;
    copy_stage(0); cp_commit();
    copy_stage(1); cp_commit();

    for (int s = 0; s < nst; s++) {
        asm volatile("cp.async.wait_group 1;" ::: "memory");
        __syncthreads();
        if (s + 2 < nst) copy_stage(s + 2);
        cp_commit();

        const int buf = s % STAGES;
        const float* as = reinterpret_cast<const float*>(smem + buf * STAGE_BYTES);
        const float* bs = reinterpret_cast<const float*>(smem + buf * STAGE_BYTES + A_BYTES);

        #pragma unroll
        for (int ks = 0; ks < 4; ks++) {
            const int kk = ks * 8 + ctig;
            uint32_t af[4][4];
            #pragma unroll
            for (int mt = 0; mt < 4; mt++) {
                int m0 = warpM * 64 + mt * 16 + gid;
                af[mt][0] = __float_as_uint(as[m0 * SA + kk]);
                af[mt][1] = __float_as_uint(as[(m0 + 8) * SA + kk]);
                af[mt][2] = __float_as_uint(as[m0 * SA + kk + 4]);
                af[mt][3] = __float_as_uint(as[(m0 + 8) * SA + kk + 4]);
            }
            if (round_a) {
                #pragma unroll
                for (int mt = 0; mt < 4; mt++)
                    #pragma unroll
                    for (int i = 0; i < 4; i++)
                        af[mt][i] = f2tf32(__uint_as_float(af[mt][i]));
            }
            uint32_t bf[4][2];
            #pragma unroll
            for (int nt = 0; nt < 4; nt++) {
                int n0 = warpN * 32 + nt * 8 + gid;
                bf[nt][0] = __float_as_uint(bs[kk * SB + n0]);
                bf[nt][1] = __float_as_uint(bs[(kk + 4) * SB + n0]);
            }
            #pragma unroll
            for (int mt = 0; mt < 4; mt++)
                #pragma unroll
                for (int nt = 0; nt < 4; nt++)
                    mma_tf32(acc[mt][nt], af[mt], bf[nt], acc[mt][nt]);
        }
    }

    // -------- epilogue: optional BN + ReLU (+ tf32 rounding), store --------
    #pragma unroll
    for (int nt = 0; nt < 4; nt++) {
        int col = ccol0 + warpN * 32 + nt * 8 + 2 * ctig;
        float sc0 = 1.f, sc1 = 1.f, sh0 = 0.f, sh1 = 0.f;
        if (scale) {
            sc0 = __ldg(scale + col);     sc1 = __ldg(scale + col + 1);
            sh0 = __ldg(shift + col);     sh1 = __ldg(shift + col + 1);
        }
        #pragma unroll
        for (int mt = 0; mt < 4; mt++) {
            int row = crow0 + warpM * 64 + mt * 16 + gid;
            float v0 = acc[mt][nt][0], v1 = acc[mt][nt][1];
            float v2 = acc[mt][nt][2], v3 = acc[mt][nt][3];
            if (scale) {
                v0 = fmaf(v0, sc0, sh0); v1 = fmaf(v1, sc1, sh1);
                v2 = fmaf(v2, sc0, sh0); v3 = fmaf(v3, sc1, sh1);
            }
            if (relu) {
                v0 = fmaxf(v0, 0.f); v1 = fmaxf(v1, 0.f);
                v2 = fmaxf(v2, 0.f); v3 = fmaxf(v3, 0.f);
            }
            if (round_out) {
                v0 = tf32f(v0); v1 = tf32f(v1); v2 = tf32f(v2); v3 = tf32f(v3);
            }
            if (row < M)
                *reinterpret_cast<float2*>(C + (size_t)row * Nn + col) =
                    make_float2(v0, v1);
            if (row + 8 < M)
                *reinterpret_cast<float2*>(C + (size_t)(row + 8) * Nn + col) =
                    make_float2(v2, v3);
        }
    }
}

extern "C" void kernel_launch(void* const* d_in, const int* in_sizes, int n_in,
                              void* d_out, int out_size) {
    const float* x        = (const float*)d_in[0];
    const int*   adj_src  = (const int*)  d_in[1];
    const int*   adj_dst  = (const int*)  d_in[2];
    const float* adj_vals = (const float*)d_in[3];
    const float* eps      = (const float*)d_in[4];
    const float* W0       = (const float*)d_in[5];
    const float* W1       = (const float*)d_in[6];
    const float* gamma    = (const float*)d_in[7];
    const float* beta     = (const float*)d_in[8];
    const float* bn_mean  = (const float*)d_in[9];
    const float* bn_var   = (const float*)d_in[10];
    float* out = (float*)d_out;

    int N = in_sizes[0] / D_IN;
    int E = in_sizes[1];

    void* p;
    cudaGetSymbolAddress(&p, g_agg);   float* agg   = (float*)p;
    cudaGetSymbolAddress(&p, g_h);     float* h     = (float*)p;
    cudaGetSymbolAddress(&p, g_w0r);   float* w0r   = (float*)p;
    cudaGetSymbolAddress(&p, g_w1r);   float* w1r   = (float*)p;
    cudaGetSymbolAddress(&p, g_scale); float* scale = (float*)p;
    cudaGetSymbolAddress(&p, g_shift); float* shift = (float*)p;

    cudaFuncSetAttribute(pipe_gemm_kernel,
                         cudaFuncAttributeMaxDynamicSharedMemorySize, GEMM_SMEM);

    // launch 1) agg = eps*x + BN params + rounded weights (merged)
    int n4 = N * (D_IN / 4);
    int ptot = (n4 > D_OUT * D_OUT) ? n4 : D_OUT * D_OUT;
    init_prep_kernel<<<(ptot + 255) / 256, 256>>>(x, eps, gamma, beta,
                                                  bn_mean, bn_var, W0, W1, n4);

    // launch 2) scatter edges into agg (vectorized L2 reductions)
    int work = E * (D_IN / 4);
    edge_scatter_kernel<<<(work + 255) / 256, 256>>>(x, adj_src, adj_dst, adj_vals, E);

    dim3 grid(D_OUT / 128, (N + 127) / 128);
    // launch 3) h = round_tf32(relu(BN(agg @ W0))), A rounded in-kernel
    pipe_gemm_kernel<<<grid, 256, GEMM_SMEM>>>(agg, w0r, h, N, D_OUT, D_IN,
                                               scale, shift, 1, 1, 1);
    // launch 4) out = h @ W1  (profiled slot)
    pipe_gemm_kernel<<<grid, 256, GEMM_SMEM>>>(h, w1r, out, N, D_OUT, D_OUT,
                                               nullptr, nullptr, 0, 0, 0);
}

// round 9
// speedup vs baseline: 1.4184x; 1.0582x over previous
#include <cuda_runtime.h>
#include <cuda_bf16.h>
#include <cstdint>
#include <cstddef>

#define D_IN   96
#define D_OUT  256
#define MAXN   50000

// -------- scratch (device globals; no allocation allowed) --------
__device__ __align__(16) float g_agg[(size_t)MAXN * D_IN];    // 19.2 MB
__device__ __align__(16) float g_w0r[D_IN * D_OUT];
__device__ __align__(16) float g_w1r[D_OUT * D_OUT];
__device__ __align__(16) float g_scale[D_OUT];
__device__ __align__(16) float g_shift[D_OUT];

// ---------------- helpers ----------------
__device__ __forceinline__ uint32_t f2tf32(float f) {
    uint32_t u;
    asm("cvt.rna.tf32.f32 %0, %1;" : "=r"(u) : "f"(f));
    return u;
}
__device__ __forceinline__ float tf32f(float f) { return __uint_as_float(f2tf32(f)); }

__device__ __forceinline__ uint32_t smem_u32(const void* p) {
    uint32_t a;
    asm("{ .reg .u64 t; cvta.to.shared.u64 t, %1; cvt.u32.u64 %0, t; }"
        : "=r"(a) : "l"(p));
    return a;
}

__device__ __forceinline__ void mma_tf32(float d[4], const uint32_t a[4],
                                         const uint32_t b[2], const float c[4]) {
    asm volatile(
        "mma.sync.aligned.m16n8k8.row.col.f32.tf32.tf32.f32 "
        "{%0,%1,%2,%3}, {%4,%5,%6,%7}, {%8,%9}, {%10,%11,%12,%13};"
        : "=f"(d[0]), "=f"(d[1]), "=f"(d[2]), "=f"(d[3])
        : "r"(a[0]), "r"(a[1]), "r"(a[2]), "r"(a[3]),
          "r"(b[0]), "r"(b[1]),
          "f"(c[0]), "f"(c[1]), "f"(c[2]), "f"(c[3]));
}

__device__ __forceinline__ void cp_async16(uint32_t dst, const void* src, uint32_t sz) {
    asm volatile("cp.async.cg.shared.global [%0], [%1], 16, %2;"
                 :: "r"(dst), "l"(src), "r"(sz) : "memory");
}
__device__ __forceinline__ void cp_commit() {
    asm volatile("cp.async.commit_group;" ::: "memory");
}

// -------- kernel 1: agg = eps * x --------
__global__ void init_agg_kernel(const float* __restrict__ x,
                                const float* __restrict__ eps, int n4) {
    int i = blockIdx.x * blockDim.x + threadIdx.x;
    if (i >= n4) return;
    float e = eps[0];
    float4 xv = reinterpret_cast<const float4*>(x)[i];
    reinterpret_cast<float4*>(g_agg)[i] =
        make_float4(e * xv.x, e * xv.y, e * xv.z, e * xv.w);
}

// -------- kernel 2: BN params + rounded weight copies --------
__global__ void prep_kernel(const float* __restrict__ gamma,
                            const float* __restrict__ beta,
                            const float* __restrict__ mean,
                            const float* __restrict__ var,
                            const float* __restrict__ W0,
                            const float* __restrict__ W1) {
    int t = blockIdx.x * blockDim.x + threadIdx.x;
    if (t < D_OUT) {
        float s = gamma[t] * rsqrtf(var[t] + 1e-3f);
        g_scale[t] = s;
        g_shift[t] = beta[t] - mean[t] * s;
    }
    const int N0 = D_IN * D_OUT;
    if (t < N0)            g_w0r[t] = tf32f(W0[t]);
    if (t < D_OUT * D_OUT) g_w1r[t] = tf32f(W1[t]);
}

// -------- vectorized global reduction (sm_90+) --------
__device__ __forceinline__ void red_add_v4(float* addr, float4 v) {
    asm volatile("red.global.add.v4.f32 [%0], {%1, %2, %3, %4};"
                 :: "l"(addr), "f"(v.x), "f"(v.y), "f"(v.z), "f"(v.w)
                 : "memory");
}

// -------- kernel 3: edge scatter  agg[dst] += vals * x[src] --------
__global__ void edge_scatter_kernel(const float* __restrict__ x,
                                    const int* __restrict__ src,
                                    const int* __restrict__ dst,
                                    const float* __restrict__ vals, int E) {
    int idx = blockIdx.x * blockDim.x + threadIdx.x;
    int e = idx / 24;
    if (e >= E) return;
    int c = idx - e * 24;
    int s = __ldg(src + e);
    int d = __ldg(dst + e);
    float v = __ldg(vals + e);
    float4 xv = __ldg(reinterpret_cast<const float4*>(x + (size_t)s * D_IN) + c);
    red_add_v4(g_agg + (size_t)d * D_IN + c * 4,
               make_float4(v * xv.x, v * xv.y, v * xv.z, v * xv.w));
}

// =================== kernel 4: fused GEMM1 + BN/ReLU + GEMM2 ===================
// Block: 128 rows x 256 cols. 8 warps, warp tile 64x64 (2M x 4N).
// Phase 1: h_smem[128x256] = round_tf32(relu(BN(agg@W0))), K=96, BK=16.
// Phase 2: out = h_smem @ W1, K=256, BK=16, A-fragments straight from smem.
// h stride 260 (bank 4*gid+ctig), A-stage stride 20 (20*gid distinct),
// W-stage stride 264 (bank 8*ctig+gid). 3-stage cp.async arena shared by phases.
#define SAH 260
#define H_WORDS (128 * SAH)                  // 33280 (133120 B)
#define SA1 20
#define SW1 264
#define A1_BYTES (128 * SA1 * 4)             // 10240
#define W1_BYTES (16 * SW1 * 4)              // 16896
#define STG_BYTES (A1_BYTES + W1_BYTES)      // 27136
#define ARENA_BYTES (3 * STG_BYTES)          // 81408
#define FUSED_SMEM (H_WORDS * 4 + ARENA_BYTES)  // 214528

__global__ __launch_bounds__(256) void fused_gemm_kernel(
    const float* __restrict__ A, const float* __restrict__ W0r,
    const float* __restrict__ W1r, float* __restrict__ out, int M)
{
    extern __shared__ float smem[];
    float* hs = smem;
    char* arena = reinterpret_cast<char*>(smem) + H_WORDS * 4;
    const uint32_t sb_ar = smem_u32(arena);

    const int tid  = threadIdx.x;
    const int lane = tid & 31;
    const int warp = tid >> 5;
    const int warpM = warp & 1;        // 2 x 64 rows
    const int warpN = warp >> 1;       // 4 x 64 cols
    const int gid  = lane >> 2;
    const int ctig = lane & 3;
    const int crow0 = blockIdx.x * 128;

    float acc[4][8][4];
    #pragma unroll
    for (int mt = 0; mt < 4; mt++)
        #pragma unroll
        for (int nt = 0; nt < 8; nt++)
            #pragma unroll
            for (int i = 0; i < 4; i++) acc[mt][nt][i] = 0.f;

    // ---------------- phase 1: h = round(relu(BN(agg @ W0))) ----------------
    auto copy_p1 = [&](int s) {
        const uint32_t ab = sb_ar + (s % 3) * STG_BYTES;
        const uint32_t wb = ab + A1_BYTES;
        const int k0 = s << 4;
        #pragma unroll
        for (int j = 0; j < 2; j++) {         // A: 128 rows x 16 floats
            int id = tid + j * 256;
            int row = id >> 2, ch = id & 3;
            int gr = crow0 + row;
            int grc = gr < M ? gr : (M - 1);
            cp_async16(ab + (uint32_t)(row * SA1 + ch * 4) * 4,
                       A + (size_t)grc * D_IN + k0 + ch * 4, gr < M ? 16u : 0u);
        }
        #pragma unroll
        for (int j = 0; j < 4; j++) {         // W0: 16 rows x 256 floats
            int id = tid + j * 256;
            int kr = id >> 6, nb = (id & 63) << 2;
            cp_async16(wb + (uint32_t)(kr * SW1 + nb) * 4,
                       W0r + (size_t)(k0 + kr) * D_OUT + nb, 16u);
        }
    };

    copy_p1(0); cp_commit();
    copy_p1(1); cp_commit();

    for (int s = 0; s < 6; s++) {
        asm volatile("cp.async.wait_group 1;" ::: "memory");
        __syncthreads();
        if (s + 2 < 6) copy_p1(s + 2);
        cp_commit();

        const float* as = reinterpret_cast<const float*>(arena + (s % 3) * STG_BYTES);
        const float* ws = reinterpret_cast<const float*>(arena + (s % 3) * STG_BYTES + A1_BYTES);

        #pragma unroll
        for (int ks = 0; ks < 2; ks++) {
            const int kk = ks * 8 + ctig;
            uint32_t af[4][4];
            #pragma unroll
            for (int mt = 0; mt < 4; mt++) {
                int m0 = warpM * 64 + mt * 16 + gid;
                af[mt][0] = f2tf32(as[m0 * SA1 + kk]);
                af[mt][1] = f2tf32(as[(m0 + 8) * SA1 + kk]);
                af[mt][2] = f2tf32(as[m0 * SA1 + kk + 4]);
                af[mt][3] = f2tf32(as[(m0 + 8) * SA1 + kk + 4]);
            }
            uint32_t bf[8][2];
            #pragma unroll
            for (int nt = 0; nt < 8; nt++) {
                int n0 = warpN * 64 + nt * 8 + gid;
                bf[nt][0] = __float_as_uint(ws[kk * SW1 + n0]);
                bf[nt][1] = __float_as_uint(ws[(kk + 4) * SW1 + n0]);
            }
            #pragma unroll
            for (int mt = 0; mt < 4; mt++)
                #pragma unroll
                for (int nt = 0; nt < 8; nt++)
                    mma_tf32(acc[mt][nt], af[mt], bf[nt], acc[mt][nt]);
        }
    }

    // phase-1 epilogue: BN + ReLU + tf32 round -> h smem
    #pragma unroll
    for (int nt = 0; nt < 8; nt++) {
        int col = warpN * 64 + nt * 8 + 2 * ctig;
        float sc0 = g_scale[col], sc1 = g_scale[col + 1];
        float sh0 = g_shift[col], sh1 = g_shift[col + 1];
        #pragma unroll
        for (int mt = 0; mt < 4; mt++) {
            int r = warpM * 64 + mt * 16 + gid;
            float v0 = tf32f(fmaxf(fmaf(acc[mt][nt][0], sc0, sh0), 0.f));
            float v1 = tf32f(fmaxf(fmaf(acc[mt][nt][1], sc1, sh1), 0.f));
            float v2 = tf32f(fmaxf(fmaf(acc[mt][nt][2], sc0, sh0), 0.f));
            float v3 = tf32f(fmaxf(fmaf(acc[mt][nt][3], sc1, sh1), 0.f));
            *reinterpret_cast<float2*>(&hs[r * SAH + col])       = make_float2(v0, v1);
            *reinterpret_cast<float2*>(&hs[(r + 8) * SAH + col]) = make_float2(v2, v3);
        }
    }
    __syncthreads();   // h visible; arena free for phase 2

    // ---------------- phase 2: out = h @ W1 ----------------
    #pragma unroll
    for (int mt = 0; mt < 4; mt++)
        #pragma unroll
        for (int nt = 0; nt < 8; nt++)
            #pragma unroll
            for (int i = 0; i < 4; i++) acc[mt][nt][i] = 0.f;

    auto copy_p2 = [&](int s) {
        const uint32_t wb = sb_ar + (s % 3) * STG_BYTES + A1_BYTES;
        const int k0 = s << 4;
        #pragma unroll
        for (int j = 0; j < 4; j++) {
            int id = tid + j * 256;
            int kr = id >> 6, nb = (id & 63) << 2;
            cp_async16(wb + (uint32_t)(kr * SW1 + nb) * 4,
                       W1r + (size_t)(k0 + kr) * D_OUT + nb, 16u);
        }
    };

    copy_p2(0); cp_commit();
    copy_p2(1); cp_commit();

    for (int s = 0; s < 16; s++) {
        asm volatile("cp.async.wait_group 1;" ::: "memory");
        __syncthreads();
        if (s + 2 < 16) copy_p2(s + 2);
        cp_commit();

        const float* ws = reinterpret_cast<const float*>(arena + (s % 3) * STG_BYTES + A1_BYTES);

        #pragma unroll
        for (int ks = 0; ks < 2; ks++) {
            const int kkl = ks * 8 + ctig;
            const int kg = s * 16 + kkl;
            uint32_t af[4][4];
            #pragma unroll
            for (int mt = 0; mt < 4; mt++) {
                int m0 = warpM * 64 + mt * 16 + gid;
                af[mt][0] = __float_as_uint(hs[m0 * SAH + kg]);
                af[mt][1] = __float_as_uint(hs[(m0 + 8) * SAH + kg]);
                af[mt][2] = __float_as_uint(hs[m0 * SAH + kg + 4]);
                af[mt][3] = __float_as_uint(hs[(m0 + 8) * SAH + kg + 4]);
            }
            uint32_t bf[8][2];
            #pragma unroll
            for (int nt = 0; nt < 8; nt++) {
                int n0 = warpN * 64 + nt * 8 + gid;
                bf[nt][0] = __float_as_uint(ws[kkl * SW1 + n0]);
                bf[nt][1] = __float_as_uint(ws[(kkl + 4) * SW1 + n0]);
            }
            #pragma unroll
            for (int mt = 0; mt < 4; mt++)
                #pragma unroll
                for (int nt = 0; nt < 8; nt++)
                    mma_tf32(acc[mt][nt], af[mt], bf[nt], acc[mt][nt]);
        }
    }

    // phase-2 epilogue: store out
    #pragma unroll
    for (int nt = 0; nt < 8; nt++) {
        int col = warpN * 64 + nt * 8 + 2 * ctig;
        #pragma unroll
        for (int mt = 0; mt < 4; mt++) {
            int row = crow0 + warpM * 64 + mt * 16 + gid;
            if (row < M)
                *reinterpret_cast<float2*>(out + (size_t)row * D_OUT + col) =
                    make_float2(acc[mt][nt][0], acc[mt][nt][1]);
            if (row + 8 < M)
                *reinterpret_cast<float2*>(out + (size_t)(row + 8) * D_OUT + col) =
                    make_float2(acc[mt][nt][2], acc[mt][nt][3]);
        }
    }
}

extern "C" void kernel_launch(void* const* d_in, const int* in_sizes, int n_in,
                              void* d_out, int out_size) {
    const float* x        = (const float*)d_in[0];
    const int*   adj_src  = (const int*)  d_in[1];
    const int*   adj_dst  = (const int*)  d_in[2];
    const float* adj_vals = (const float*)d_in[3];
    const float* eps      = (const float*)d_in[4];
    const float* W0       = (const float*)d_in[5];
    const float* W1       = (const float*)d_in[6];
    const float* gamma    = (const float*)d_in[7];
    const float* beta     = (const float*)d_in[8];
    const float* bn_mean  = (const float*)d_in[9];
    const float* bn_var   = (const float*)d_in[10];
    float* out = (float*)d_out;

    int N = in_sizes[0] / D_IN;
    int E = in_sizes[1];

    void* p;
    cudaGetSymbolAddress(&p, g_agg);   float* agg   = (float*)p;
    cudaGetSymbolAddress(&p, g_w0r);   float* w0r   = (float*)p;
    cudaGetSymbolAddress(&p, g_w1r);   float* w1r   = (float*)p;

    cudaFuncSetAttribute(fused_gemm_kernel,
                         cudaFuncAttributeMaxDynamicSharedMemorySize, FUSED_SMEM);

    // launch 1) agg = eps * x
    int n4 = N * (D_IN / 4);
    init_agg_kernel<<<(n4 + 255) / 256, 256>>>(x, eps, n4);

    // launch 2) BN params + rounded weights
    prep_kernel<<<(D_OUT * D_OUT + 255) / 256, 256>>>(gamma, beta, bn_mean, bn_var, W0, W1);

    // launch 3) scatter edges into agg (vectorized L2 reductions)
    int work = E * (D_IN / 4);
    edge_scatter_kernel<<<(work + 255) / 256, 256>>>(x, adj_src, adj_dst, adj_vals, E);

    // launch 4) fused GEMM1 + BN/ReLU + GEMM2   (profiled slot)
    fused_gemm_kernel<<<(N + 127) / 128, 256, FUSED_SMEM>>>(agg, w0r, w1r, out, N);
}

// round 10
// speedup vs baseline: 1.5071x; 1.0625x over previous
#include <cuda_runtime.h>
#include <cuda_bf16.h>
#include <cstdint>
#include <cstddef>

#define D_IN   96
#define D_OUT  256
#define MAXN   50000

// -------- scratch (device globals; no allocation allowed) --------
__device__ __align__(16) float g_agg[(size_t)MAXN * D_IN];    // 19.2 MB
__device__ __align__(16) float g_w0r[D_IN * D_OUT];
__device__ __align__(16) float g_w1r[D_OUT * D_OUT];
__device__ __align__(16) float g_scale[D_OUT];
__device__ __align__(16) float g_shift[D_OUT];

// ---------------- helpers ----------------
__device__ __forceinline__ uint32_t f2tf32(float f) {
    uint32_t u;
    asm("cvt.rna.tf32.f32 %0, %1;" : "=r"(u) : "f"(f));
    return u;
}
__device__ __forceinline__ float tf32f(float f) { return __uint_as_float(f2tf32(f)); }

__device__ __forceinline__ uint32_t smem_u32(const void* p) {
    uint32_t a;
    asm("{ .reg .u64 t; cvta.to.shared.u64 t, %1; cvt.u32.u64 %0, t; }"
        : "=r"(a) : "l"(p));
    return a;
}

__device__ __forceinline__ void mma_tf32(float d[4], const uint32_t a[4],
                                         const uint32_t b[2], const float c[4]) {
    asm volatile(
        "mma.sync.aligned.m16n8k8.row.col.f32.tf32.tf32.f32 "
        "{%0,%1,%2,%3}, {%4,%5,%6,%7}, {%8,%9}, {%10,%11,%12,%13};"
        : "=f"(d[0]), "=f"(d[1]), "=f"(d[2]), "=f"(d[3])
        : "r"(a[0]), "r"(a[1]), "r"(a[2]), "r"(a[3]),
          "r"(b[0]), "r"(b[1]),
          "f"(c[0]), "f"(c[1]), "f"(c[2]), "f"(c[3]));
}

__device__ __forceinline__ void cp_async16(uint32_t dst, const void* src, uint32_t sz) {
    asm volatile("cp.async.cg.shared.global [%0], [%1], 16, %2;"
                 :: "r"(dst), "l"(src), "r"(sz) : "memory");
}
__device__ __forceinline__ void cp_commit() {
    asm volatile("cp.async.commit_group;" ::: "memory");
}

// -------- kernel 1: agg = eps*x  +  BN params  +  rounded weight copies --------
__global__ void init_prep_kernel(const float* __restrict__ x,
                                 const float* __restrict__ eps,
                                 const float* __restrict__ gamma,
                                 const float* __restrict__ beta,
                                 const float* __restrict__ mean,
                                 const float* __restrict__ var,
                                 const float* __restrict__ W0,
                                 const float* __restrict__ W1, int n4) {
    int t = blockIdx.x * blockDim.x + threadIdx.x;
    if (t < n4) {
        float e = eps[0];
        float4 xv = reinterpret_cast<const float4*>(x)[t];
        reinterpret_cast<float4*>(g_agg)[t] =
            make_float4(e * xv.x, e * xv.y, e * xv.z, e * xv.w);
    }
    if (t < D_OUT) {
        float s = gamma[t] * rsqrtf(var[t] + 1e-3f);
        g_scale[t] = s;
        g_shift[t] = beta[t] - mean[t] * s;
    }
    const int N0 = D_IN * D_OUT;
    if (t < N0)            g_w0r[t] = tf32f(W0[t]);
    if (t < D_OUT * D_OUT) g_w1r[t] = tf32f(W1[t]);
}

// -------- vectorized global reduction (sm_90+) --------
__device__ __forceinline__ void red_add_v4(float* addr, float4 v) {
    asm volatile("red.global.add.v4.f32 [%0], {%1, %2, %3, %4};"
                 :: "l"(addr), "f"(v.x), "f"(v.y), "f"(v.z), "f"(v.w)
                 : "memory");
}

// -------- kernel 2: edge scatter  agg[dst] += vals * x[src] --------
__global__ void edge_scatter_kernel(const float* __restrict__ x,
                                    const int* __restrict__ src,
                                    const int* __restrict__ dst,
                                    const float* __restrict__ vals, int E) {
    int idx = blockIdx.x * blockDim.x + threadIdx.x;
    int e = idx / 24;
    if (e >= E) return;
    int c = idx - e * 24;
    int s = __ldg(src + e);
    int d = __ldg(dst + e);
    float v = __ldg(vals + e);
    float4 xv = __ldg(reinterpret_cast<const float4*>(x + (size_t)s * D_IN) + c);
    red_add_v4(g_agg + (size_t)d * D_IN + c * 4,
               make_float4(v * xv.x, v * xv.y, v * xv.z, v * xv.w));
}

// =================== kernel 3: fused GEMM1 + BN/ReLU + GEMM2 ===================
// Block: 64 rows x 256 cols, 8 warps, warp tile 32x64 (2M x 4N).
// 110.6 KB smem -> 2 CTAs/SM (16 warps/SM, independent pipelines).
// Phase 1: h_smem[64x256] = round_tf32(relu(BN(agg@W0))), K=96, BK=16, 2-stage.
// Phase 2: out = h_smem @ W1, K=256, BK=16, A-fragments from h smem, 2-stage W.
// h stride 260 (fragment bank 4*gid+ctig); A-stage stride 20; W-stage stride 264.
#define ROWS  64
#define SAH 260
#define H_WORDS (ROWS * SAH)                 // 16640 (66560 B)
#define SA1 20
#define SW1 264
#define A1_BYTES (ROWS * SA1 * 4)            // 5120
#define W1_BYTES (16 * SW1 * 4)              // 16896
#define STG_BYTES (A1_BYTES + W1_BYTES)      // 22016
#define ARENA_BYTES (2 * STG_BYTES)          // 44032
#define FUSED_SMEM (H_WORDS * 4 + ARENA_BYTES)  // 110592

__global__ __launch_bounds__(256, 2) void fused_gemm_kernel(
    const float* __restrict__ A, const float* __restrict__ W0r,
    const float* __restrict__ W1r, float* __restrict__ out, int M)
{
    extern __shared__ float smem[];
    float* hs = smem;
    char* arena = reinterpret_cast<char*>(smem) + H_WORDS * 4;
    const uint32_t sb_ar = smem_u32(arena);

    const int tid  = threadIdx.x;
    const int lane = tid & 31;
    const int warp = tid >> 5;
    const int warpM = warp & 1;        // 2 x 32 rows
    const int warpN = warp >> 1;       // 4 x 64 cols
    const int gid  = lane >> 2;
    const int ctig = lane & 3;
    const int crow0 = blockIdx.x * ROWS;

    float acc[2][8][4];
    #pragma unroll
    for (int mt = 0; mt < 2; mt++)
        #pragma unroll
        for (int nt = 0; nt < 8; nt++)
            #pragma unroll
            for (int i = 0; i < 4; i++) acc[mt][nt][i] = 0.f;

    // ---------------- phase 1: h = round(relu(BN(agg @ W0))) ----------------
    auto copy_p1 = [&](int s) {
        const uint32_t ab = sb_ar + (s & 1) * STG_BYTES;
        const uint32_t wb = ab + A1_BYTES;
        const int k0 = s << 4;
        {   // A: 64 rows x 16 floats = 256 float4, 1 per thread
            int row = tid >> 2, ch = tid & 3;
            int gr = crow0 + row;
            int grc = gr < M ? gr : (M - 1);
            cp_async16(ab + (uint32_t)(row * SA1 + ch * 4) * 4,
                       A + (size_t)grc * D_IN + k0 + ch * 4, gr < M ? 16u : 0u);
        }
        #pragma unroll
        for (int j = 0; j < 4; j++) {   // W0: 16 rows x 256 floats
            int id = tid + j * 256;
            int kr = id >> 6, nb = (id & 63) << 2;
            cp_async16(wb + (uint32_t)(kr * SW1 + nb) * 4,
                       W0r + (size_t)(k0 + kr) * D_OUT + nb, 16u);
        }
    };

    copy_p1(0); cp_commit();
    copy_p1(1); cp_commit();

    for (int s = 0; s < 6; s++) {
        asm volatile("cp.async.wait_group 1;" ::: "memory");
        __syncthreads();

        const char* stg = arena + (s & 1) * STG_BYTES;
        const float* as = reinterpret_cast<const float*>(stg);
        const float* ws = reinterpret_cast<const float*>(stg + A1_BYTES);

        #pragma unroll
        for (int ks = 0; ks < 2; ks++) {
            const int kk = ks * 8 + ctig;
            uint32_t af[2][4];
            #pragma unroll
            for (int mt = 0; mt < 2; mt++) {
                int m0 = warpM * 32 + mt * 16 + gid;
                af[mt][0] = f2tf32(as[m0 * SA1 + kk]);
                af[mt][1] = f2tf32(as[(m0 + 8) * SA1 + kk]);
                af[mt][2] = f2tf32(as[m0 * SA1 + kk + 4]);
                af[mt][3] = f2tf32(as[(m0 + 8) * SA1 + kk + 4]);
            }
            uint32_t bf[8][2];
            #pragma unroll
            for (int nt = 0; nt < 8; nt++) {
                int n0 = warpN * 64 + nt * 8 + gid;
                bf[nt][0] = __float_as_uint(ws[kk * SW1 + n0]);
                bf[nt][1] = __float_as_uint(ws[(kk + 4) * SW1 + n0]);
            }
            #pragma unroll
            for (int mt = 0; mt < 2; mt++)
                #pragma unroll
                for (int nt = 0; nt < 8; nt++)
                    mma_tf32(acc[mt][nt], af[mt], bf[nt], acc[mt][nt]);
        }

        __syncthreads();
        if (s + 2 < 6) copy_p1(s + 2);
        cp_commit();
    }

    // phase-1 epilogue: BN + ReLU + tf32 round -> h smem
    #pragma unroll
    for (int nt = 0; nt < 8; nt++) {
        int col = warpN * 64 + nt * 8 + 2 * ctig;
        float sc0 = g_scale[col], sc1 = g_scale[col + 1];
        float sh0 = g_shift[col], sh1 = g_shift[col + 1];
        #pragma unroll
        for (int mt = 0; mt < 2; mt++) {
            int r = warpM * 32 + mt * 16 + gid;
            float v0 = tf32f(fmaxf(fmaf(acc[mt][nt][0], sc0, sh0), 0.f));
            float v1 = tf32f(fmaxf(fmaf(acc[mt][nt][1], sc1, sh1), 0.f));
            float v2 = tf32f(fmaxf(fmaf(acc[mt][nt][2], sc0, sh0), 0.f));
            float v3 = tf32f(fmaxf(fmaf(acc[mt][nt][3], sc1, sh1), 0.f));
            *reinterpret_cast<float2*>(&hs[r * SAH + col])       = make_float2(v0, v1);
            *reinterpret_cast<float2*>(&hs[(r + 8) * SAH + col]) = make_float2(v2, v3);
        }
    }

    // ---------------- phase 2: out = h @ W1 ----------------
    #pragma unroll
    for (int mt = 0; mt < 2; mt++)
        #pragma unroll
        for (int nt = 0; nt < 8; nt++)
            #pragma unroll
            for (int i = 0; i < 4; i++) acc[mt][nt][i] = 0.f;

    auto copy_p2 = [&](int s) {
        const uint32_t wb = sb_ar + (s & 1) * STG_BYTES + A1_BYTES;
        const int k0 = s << 4;
        #pragma unroll
        for (int j = 0; j < 4; j++) {
            int id = tid + j * 256;
            int kr = id >> 6, nb = (id & 63) << 2;
            cp_async16(wb + (uint32_t)(kr * SW1 + nb) * 4,
                       W1r + (size_t)(k0 + kr) * D_OUT + nb, 16u);
        }
    };

    __syncthreads();            // h visible to all warps; arena free
    copy_p2(0); cp_commit();
    copy_p2(1); cp_commit();

    for (int s = 0; s < 16; s++) {
        asm volatile("cp.async.wait_group 1;" ::: "memory");
        __syncthreads();

        const float* ws = reinterpret_cast<const float*>(
            arena + (s & 1) * STG_BYTES + A1_BYTES);

        #pragma unroll
        for (int ks = 0; ks < 2; ks++) {
            const int kkl = ks * 8 + ctig;
            const int kg = s * 16 + kkl;
            uint32_t af[2][4];
            #pragma unroll
            for (int mt = 0; mt < 2; mt++) {
                int m0 = warpM * 32 + mt * 16 + gid;
                af[mt][0] = __float_as_uint(hs[m0 * SAH + kg]);
                af[mt][1] = __float_as_uint(hs[(m0 + 8) * SAH + kg]);
                af[mt][2] = __float_as_uint(hs[m0 * SAH + kg + 4]);
                af[mt][3] = __float_as_uint(hs[(m0 + 8) * SAH + kg + 4]);
            }
            uint32_t bf[8][2];
            #pragma unroll
            for (int nt = 0; nt < 8; nt++) {
                int n0 = warpN * 64 + nt * 8 + gid;
                bf[nt][0] = __float_as_uint(ws[kkl * SW1 + n0]);
                bf[nt][1] = __float_as_uint(ws[(kkl + 4) * SW1 + n0]);
            }
            #pragma unroll
            for (int mt = 0; mt < 2; mt++)
                #pragma unroll
                for (int nt = 0; nt < 8; nt++)
                    mma_tf32(acc[mt][nt], af[mt], bf[nt], acc[mt][nt]);
        }

        __syncthreads();
        if (s + 2 < 16) copy_p2(s + 2);
        cp_commit();
    }

    // phase-2 epilogue: store out
    #pragma unroll
    for (int nt = 0; nt < 8; nt++) {
        int col = warpN * 64 + nt * 8 + 2 * ctig;
        #pragma unroll
        for (int mt = 0; mt < 2; mt++) {
            int row = crow0 + warpM * 32 + mt * 16 + gid;
            if (row < M)
                *reinterpret_cast<float2*>(out + (size_t)row * D_OUT + col) =
                    make_float2(acc[mt][nt][0], acc[mt][nt][1]);
            if (row + 8 < M)
                *reinterpret_cast<float2*>(out + (size_t)(row + 8) * D_OUT + col) =
                    make_float2(acc[mt][nt][2], acc[mt][nt][3]);
        }
    }
}

extern "C" void kernel_launch(void* const* d_in, const int* in_sizes, int n_in,
                              void* d_out, int out_size) {
    const float* x        = (const float*)d_in[0];
    const int*   adj_src  = (const int*)  d_in[1];
    const int*   adj_dst  = (const int*)  d_in[2];
    const float* adj_vals = (const float*)d_in[3];
    const float* eps      = (const float*)d_in[4];
    const float* W0       = (const float*)d_in[5];
    const float* W1       = (const float*)d_in[6];
    const float* gamma    = (const float*)d_in[7];
    const float* beta     = (const float*)d_in[8];
    const float* bn_mean  = (const float*)d_in[9];
    const float* bn_var   = (const float*)d_in[10];
    float* out = (float*)d_out;

    int N = in_sizes[0] / D_IN;
    int E = in_sizes[1];

    void* p;
    cudaGetSymbolAddress(&p, g_agg);   float* agg   = (float*)p;
    cudaGetSymbolAddress(&p, g_w0r);   float* w0r   = (float*)p;
    cudaGetSymbolAddress(&p, g_w1r);   float* w1r   = (float*)p;

    cudaFuncSetAttribute(fused_gemm_kernel,
                         cudaFuncAttributeMaxDynamicSharedMemorySize, FUSED_SMEM);

    // launch 1) agg = eps*x + BN params + rounded weights (merged)
    int n4 = N * (D_IN / 4);
    int ptot = (n4 > D_OUT * D_OUT) ? n4 : D_OUT * D_OUT;
    init_prep_kernel<<<(ptot + 255) / 256, 256>>>(x, eps, gamma, beta,
                                                  bn_mean, bn_var, W0, W1, n4);

    // launch 2) scatter edges into agg (vectorized L2 reductions)
    int work = E * (D_IN / 4);
    edge_scatter_kernel<<<(work + 255) / 256, 256>>>(x, adj_src, adj_dst, adj_vals, E);

    // launch 3) fused GEMM1 + BN/ReLU + GEMM2
    fused_gemm_kernel<<<(N + ROWS - 1) / ROWS, 256, FUSED_SMEM>>>(agg, w0r, w1r, out, N);
}

// round 11
// speedup vs baseline: 1.5437x; 1.0243x over previous
#include <cuda_runtime.h>
#include <cuda_bf16.h>
#include <cstdint>
#include <cstddef>

#define D_IN   96
#define D_OUT  256
#define MAXN   50000

// -------- scratch (device globals; no allocation allowed) --------
__device__ __align__(16) float g_agg[(size_t)MAXN * D_IN];    // 19.2 MB
// W pair-layout: [K/16 chunks][8 pairs][256 n][2]  (entry = (W[k][n], W[k+4][n]))
__device__ __align__(16) float g_w0p[6 * 8 * D_OUT * 2];      // 24576
__device__ __align__(16) float g_w1p[16 * 8 * D_OUT * 2];     // 65536
__device__ __align__(16) float g_scale[D_OUT];
__device__ __align__(16) float g_shift[D_OUT];

// ---------------- helpers ----------------
__device__ __forceinline__ uint32_t f2tf32(float f) {
    uint32_t u;
    asm("cvt.rna.tf32.f32 %0, %1;" : "=r"(u) : "f"(f));
    return u;
}
__device__ __forceinline__ float tf32f(float f) { return __uint_as_float(f2tf32(f)); }

__device__ __forceinline__ uint32_t smem_u32(const void* p) {
    uint32_t a;
    asm("{ .reg .u64 t; cvta.to.shared.u64 t, %1; cvt.u32.u64 %0, t; }"
        : "=r"(a) : "l"(p));
    return a;
}

__device__ __forceinline__ void mma_tf32(float d[4], const uint32_t a[4],
                                         const uint32_t b[2], const float c[4]) {
    asm volatile(
        "mma.sync.aligned.m16n8k8.row.col.f32.tf32.tf32.f32 "
        "{%0,%1,%2,%3}, {%4,%5,%6,%7}, {%8,%9}, {%10,%11,%12,%13};"
        : "=f"(d[0]), "=f"(d[1]), "=f"(d[2]), "=f"(d[3])
        : "r"(a[0]), "r"(a[1]), "r"(a[2]), "r"(a[3]),
          "r"(b[0]), "r"(b[1]),
          "f"(c[0]), "f"(c[1]), "f"(c[2]), "f"(c[3]));
}

__device__ __forceinline__ void cp_async16(uint32_t dst, const void* src, uint32_t sz) {
    asm volatile("cp.async.cg.shared.global [%0], [%1], 16, %2;"
                 :: "r"(dst), "l"(src), "r"(sz) : "memory");
}
__device__ __forceinline__ void cp_commit() {
    asm volatile("cp.async.commit_group;" ::: "memory");
}

// -------- kernel 1: agg = eps*x + BN params + paired/rounded weights --------
__global__ void init_prep_kernel(const float* __restrict__ x,
                                 const float* __restrict__ eps,
                                 const float* __restrict__ gamma,
                                 const float* __restrict__ beta,
                                 const float* __restrict__ mean,
                                 const float* __restrict__ var,
                                 const float* __restrict__ W0,
                                 const float* __restrict__ W1, int n4) {
    int t = blockIdx.x * blockDim.x + threadIdx.x;
    if (t < n4) {
        float e = eps[0];
        float4 xv = reinterpret_cast<const float4*>(x)[t];
        reinterpret_cast<float4*>(g_agg)[t] =
            make_float4(e * xv.x, e * xv.y, e * xv.z, e * xv.w);
    }
    if (t < D_OUT) {
        float s = gamma[t] * rsqrtf(var[t] + 1e-3f);
        g_scale[t] = s;
        g_shift[t] = beta[t] - mean[t] * s;
    }
    // W1 pair layout: t in [0, 65536)
    if (t < 16 * 8 * D_OUT * 2) {
        int j  = t & 1;
        int n  = (t >> 1) & 255;
        int pp = (t >> 9) & 7;
        int kc = t >> 12;
        int k  = kc * 16 + ((pp >> 2) << 3) + (pp & 3) + (j << 2);
        g_w1p[t] = tf32f(W1[(size_t)k * D_OUT + n]);
    }
    // W0 pair layout: t in [0, 24576)
    if (t < 6 * 8 * D_OUT * 2) {
        int j  = t & 1;
        int n  = (t >> 1) & 255;
        int pp = (t >> 9) & 7;
        int kc = t >> 12;
        int k  = kc * 16 + ((pp >> 2) << 3) + (pp & 3) + (j << 2);
        g_w0p[t] = tf32f(W0[(size_t)k * D_OUT + n]);
    }
}

// -------- vectorized global reduction (sm_90+) --------
__device__ __forceinline__ void red_add_v4(float* addr, float4 v) {
    asm volatile("red.global.add.v4.f32 [%0], {%1, %2, %3, %4};"
                 :: "l"(addr), "f"(v.x), "f"(v.y), "f"(v.z), "f"(v.w)
                 : "memory");
}

// -------- kernel 2: edge scatter  agg[dst] += vals * x[src] --------
__global__ void edge_scatter_kernel(const float* __restrict__ x,
                                    const int* __restrict__ src,
                                    const int* __restrict__ dst,
                                    const float* __restrict__ vals, int E) {
    int idx = blockIdx.x * blockDim.x + threadIdx.x;
    int e = idx / 24;
    if (e >= E) return;
    int c = idx - e * 24;
    int s = __ldg(src + e);
    int d = __ldg(dst + e);
    float v = __ldg(vals + e);
    float4 xv = __ldg(reinterpret_cast<const float4*>(x + (size_t)s * D_IN) + c);
    red_add_v4(g_agg + (size_t)d * D_IN + c * 4,
               make_float4(v * xv.x, v * xv.y, v * xv.z, v * xv.w));
}

// =================== kernel 3: fused GEMM1 + BN/ReLU + GEMM2 ===================
// 64 rows x 256 cols, 8 warps, warp tile 32x64. 2 CTAs/SM (110080 B smem).
// W tiles staged in (k,k+4)-paired layout: 8 pair-rows x 256 n x 8B, row
// stride 2080 B -> bf fragment = one LDS.64, banks 8*ctig + 2*gid (no conflict).
#define ROWS  64
#define SAH 260
#define H_WORDS (ROWS * SAH)                 // 16640 (66560 B)
#define SA1 20
#define A1_BYTES (ROWS * SA1 * 4)            // 5120
#define WP_ROW_B 2080                        // 260 entries * 8B
#define WP_BYTES (8 * WP_ROW_B)              // 16640
#define STG_BYTES (A1_BYTES + WP_BYTES)      // 21760
#define ARENA_BYTES (2 * STG_BYTES)          // 43520
#define FUSED_SMEM (H_WORDS * 4 + ARENA_BYTES)  // 110080

__global__ __launch_bounds__(256, 2) void fused_gemm_kernel(
    const float* __restrict__ A, const float* __restrict__ W0p,
    const float* __restrict__ W1p, float* __restrict__ out, int M)
{
    extern __shared__ float smem[];
    float* hs = smem;
    char* arena = reinterpret_cast<char*>(smem) + H_WORDS * 4;
    const uint32_t sb_ar = smem_u32(arena);

    const int tid  = threadIdx.x;
    const int lane = tid & 31;
    const int warp = tid >> 5;
    const int warpM = warp & 1;        // 2 x 32 rows
    const int warpN = warp >> 1;       // 4 x 64 cols
    const int gid  = lane >> 2;
    const int ctig = lane & 3;
    const int crow0 = blockIdx.x * ROWS;

    float acc[2][8][4];
    #pragma unroll
    for (int mt = 0; mt < 2; mt++)
        #pragma unroll
        for (int nt = 0; nt < 8; nt++)
            #pragma unroll
            for (int i = 0; i < 4; i++) acc[mt][nt][i] = 0.f;

    // W-chunk copy: 1024 x 16B (each = 2 pair-entries = 2 consecutive n)
    auto copy_w = [&](const float* Wp, int kc, uint32_t wb) {
        #pragma unroll
        for (int j = 0; j < 4; j++) {
            int id = tid + j * 256;
            int pp = id >> 7;            // 0..7
            int n2 = id & 127;           // n pair index
            cp_async16(wb + (uint32_t)(pp * WP_ROW_B + n2 * 16),
                       Wp + ((size_t)(kc * 8 + pp) * D_OUT + n2 * 2) * 2, 16u);
        }
    };
    auto copy_a = [&](int s, uint32_t ab) {
        int row = tid >> 2, ch = tid & 3;
        int gr = crow0 + row;
        int grc = gr < M ? gr : (M - 1);
        cp_async16(ab + (uint32_t)(row * SA1 + ch * 4) * 4,
                   A + (size_t)grc * D_IN + (s << 4) + ch * 4, gr < M ? 16u : 0u);
    };
    auto copy_p1 = [&](int s) {
        const uint32_t ab = sb_ar + (s & 1) * STG_BYTES;
        copy_a(s, ab);
        copy_w(W0p, s, ab + A1_BYTES);
    };

    copy_p1(0); cp_commit();
    copy_p1(1); cp_commit();

    // ---------------- phase 1: h = round(relu(BN(agg @ W0))) ----------------
    for (int s = 0; s < 6; s++) {
        asm volatile("cp.async.wait_group 1;" ::: "memory");
        __syncthreads();

        const char* stg = arena + (s & 1) * STG_BYTES;
        const float* as = reinterpret_cast<const float*>(stg);
        const char* wsb = stg + A1_BYTES;

        #pragma unroll
        for (int ks = 0; ks < 2; ks++) {
            const int kk = ks * 8 + ctig;
            uint32_t af[2][4];
            #pragma unroll
            for (int mt = 0; mt < 2; mt++) {
                int m0 = warpM * 32 + mt * 16 + gid;
                af[mt][0] = f2tf32(as[m0 * SA1 + kk]);
                af[mt][1] = f2tf32(as[(m0 + 8) * SA1 + kk]);
                af[mt][2] = f2tf32(as[m0 * SA1 + kk + 4]);
                af[mt][3] = f2tf32(as[(m0 + 8) * SA1 + kk + 4]);
            }
            const char* wrow = wsb + (ks * 4 + ctig) * WP_ROW_B;
            uint32_t bf[8][2];
            #pragma unroll
            for (int nt = 0; nt < 8; nt++) {
                int n0 = warpN * 64 + nt * 8 + gid;
                float2 wv = *reinterpret_cast<const float2*>(wrow + n0 * 8);
                bf[nt][0] = __float_as_uint(wv.x);
                bf[nt][1] = __float_as_uint(wv.y);
            }
            #pragma unroll
            for (int mt = 0; mt < 2; mt++)
                #pragma unroll
                for (int nt = 0; nt < 8; nt++)
                    mma_tf32(acc[mt][nt], af[mt], bf[nt], acc[mt][nt]);
        }

        __syncthreads();
        if (s + 2 < 6) copy_p1(s + 2);
        cp_commit();
    }

    // phase-1 epilogue: BN + ReLU + tf32 round -> h smem
    #pragma unroll
    for (int nt = 0; nt < 8; nt++) {
        int col = warpN * 64 + nt * 8 + 2 * ctig;
        float sc0 = g_scale[col], sc1 = g_scale[col + 1];
        float sh0 = g_shift[col], sh1 = g_shift[col + 1];
        #pragma unroll
        for (int mt = 0; mt < 2; mt++) {
            int r = warpM * 32 + mt * 16 + gid;
            float v0 = tf32f(fmaxf(fmaf(acc[mt][nt][0], sc0, sh0), 0.f));
            float v1 = tf32f(fmaxf(fmaf(acc[mt][nt][1], sc1, sh1), 0.f));
            float v2 = tf32f(fmaxf(fmaf(acc[mt][nt][2], sc0, sh0), 0.f));
            float v3 = tf32f(fmaxf(fmaf(acc[mt][nt][3], sc1, sh1), 0.f));
            *reinterpret_cast<float2*>(&hs[r * SAH + col])       = make_float2(v0, v1);
            *reinterpret_cast<float2*>(&hs[(r + 8) * SAH + col]) = make_float2(v2, v3);
        }
    }

    // ---------------- phase 2: out = h @ W1 ----------------
    #pragma unroll
    for (int mt = 0; mt < 2; mt++)
        #pragma unroll
        for (int nt = 0; nt < 8; nt++)
            #pragma unroll
            for (int i = 0; i < 4; i++) acc[mt][nt][i] = 0.f;

    __syncthreads();            // h visible; arena free
    copy_w(W1p, 0, sb_ar + A1_BYTES); cp_commit();
    copy_w(W1p, 1, sb_ar + STG_BYTES + A1_BYTES); cp_commit();

    for (int s = 0; s < 16; s++) {
        asm volatile("cp.async.wait_group 1;" ::: "memory");
        __syncthreads();

        const char* wsb = arena + (s & 1) * STG_BYTES + A1_BYTES;

        #pragma unroll
        for (int ks = 0; ks < 2; ks++) {
            const int kg = s * 16 + ks * 8 + ctig;
            uint32_t af[2][4];
            #pragma unroll
            for (int mt = 0; mt < 2; mt++) {
                int m0 = warpM * 32 + mt * 16 + gid;
                af[mt][0] = __float_as_uint(hs[m0 * SAH + kg]);
                af[mt][1] = __float_as_uint(hs[(m0 + 8) * SAH + kg]);
                af[mt][2] = __float_as_uint(hs[m0 * SAH + kg + 4]);
                af[mt][3] = __float_as_uint(hs[(m0 + 8) * SAH + kg + 4]);
            }
            const char* wrow = wsb + (ks * 4 + ctig) * WP_ROW_B;
            uint32_t bf[8][2];
            #pragma unroll
            for (int nt = 0; nt < 8; nt++) {
                int n0 = warpN * 64 + nt * 8 + gid;
                float2 wv = *reinterpret_cast<const float2*>(wrow + n0 * 8);
                bf[nt][0] = __float_as_uint(wv.x);
                bf[nt][1] = __float_as_uint(wv.y);
            }
            #pragma unroll
            for (int mt = 0; mt < 2; mt++)
                #pragma unroll
                for (int nt = 0; nt < 8; nt++)
                    mma_tf32(acc[mt][nt], af[mt], bf[nt], acc[mt][nt]);
        }

        __syncthreads();
        if (s + 2 < 16)
            copy_w(W1p, s + 2, sb_ar + ((s + 2) & 1) * STG_BYTES + A1_BYTES);
        cp_commit();
    }

    // phase-2 epilogue: store out
    #pragma unroll
    for (int nt = 0; nt < 8; nt++) {
        int col = warpN * 64 + nt * 8 + 2 * ctig;
        #pragma unroll
        for (int mt = 0; mt < 2; mt++) {
            int row = crow0 + warpM * 32 + mt * 16 + gid;
            if (row < M)
                *reinterpret_cast<float2*>(out + (size_t)row * D_OUT + col) =
                    make_float2(acc[mt][nt][0], acc[mt][nt][1]);
            if (row + 8 < M)
                *reinterpret_cast<float2*>(out + (size_t)(row + 8) * D_OUT + col) =
                    make_float2(acc[mt][nt][2], acc[mt][nt][3]);
        }
    }
}

extern "C" void kernel_launch(void* const* d_in, const int* in_sizes, int n_in,
                              void* d_out, int out_size) {
    const float* x        = (const float*)d_in[0];
    const int*   adj_src  = (const int*)  d_in[1];
    const int*   adj_dst  = (const int*)  d_in[2];
    const float* adj_vals = (const float*)d_in[3];
    const float* eps      = (const float*)d_in[4];
    const float* W0       = (const float*)d_in[5];
    const float* W1       = (const float*)d_in[6];
    const float* gamma    = (const float*)d_in[7];
    const float* beta     = (const float*)d_in[8];
    const float* bn_mean  = (const float*)d_in[9];
    const float* bn_var   = (const float*)d_in[10];
    float* out = (float*)d_out;

    int N = in_sizes[0] / D_IN;
    int E = in_sizes[1];

    void* p;
    cudaGetSymbolAddress(&p, g_agg);   float* agg = (float*)p;
    cudaGetSymbolAddress(&p, g_w0p);   float* w0p = (float*)p;
    cudaGetSymbolAddress(&p, g_w1p);   float* w1p = (float*)p;

    cudaFuncSetAttribute(fused_gemm_kernel,
                         cudaFuncAttributeMaxDynamicSharedMemorySize, FUSED_SMEM);

    // launch 1) agg = eps*x + BN params + paired/rounded weights
    int n4 = N * (D_IN / 4);
    int ptot = (n4 > 16 * 8 * D_OUT * 2) ? n4 : 16 * 8 * D_OUT * 2;
    init_prep_kernel<<<(ptot + 255) / 256, 256>>>(x, eps, gamma, beta,
                                                  bn_mean, bn_var, W0, W1, n4);

    // launch 2) scatter edges into agg (vectorized L2 reductions)
    int work = E * (D_IN / 4);
    edge_scatter_kernel<<<(work + 255) / 256, 256>>>(x, adj_src, adj_dst, adj_vals, E);

    // launch 3) fused GEMM1 + BN/ReLU + GEMM2
    fused_gemm_kernel<<<(N + ROWS - 1) / ROWS, 256, FUSED_SMEM>>>(agg, w0p, w1p, out, N);
}